// round 16
// baseline (speedup 1.0000x reference)
#include <cuda_runtime.h>
#include <cuda_bf16.h>
#include <cuda_fp16.h>
#include <cstdint>

// ---------------------------------------------------------------------------
// Problem constants
// ---------------------------------------------------------------------------
#define CCN   256
#define STD   12
#define FS    64
#define HALF  32
#define NIMG  (CCN*STD)          // 3072
#define DIM   2048               // FS*HALF
#define IMGE  (FS*FS)            // 4096

#define WSCALE     64.0f
#define WSCALE_INV 0.015625f

static const size_t T_FULL  = (size_t)NIMG * IMGE;
static const size_t T_SLICE = (size_t)CCN * 11 * IMGE;

// Output section offsets (floats)
static const size_t S0 = 0;                    // x
static const size_t S1 = S0 + T_FULL;          // phiX
static const size_t S2 = S1 + T_FULL;          // dephiPhiX
static const size_t S3 = S2 + T_FULL;          // kPhix
static const size_t S4 = S3 + T_FULL;          // dePhiKPhiX
static const size_t S5 = S4 + T_FULL;          // x[:,1:]
static const size_t S6 = S5 + T_SLICE;         // phiX[:,1:]

// ---------------------------------------------------------------------------
// Scratch (device globals — no runtime allocation allowed)
// ---------------------------------------------------------------------------
__device__ float  g_A [(size_t)NIMG * DIM];
__device__ float  g_B [(size_t)NIMG * DIM];
__device__ float  g_C [(size_t)NIMG * DIM];
__device__ float  g_D [(size_t)NIMG * DIM];
__device__ __half g_H0[(size_t)NIMG * DIM];    // fp16 plane (phiX path)
__device__ __half g_H1[(size_t)NIMG * DIM];    // fp16 plane (phiX path)
__device__ __half g_H2[(size_t)NIMG * DIM];    // fp16 plane (kPhix path)
__device__ __half g_H3[(size_t)NIMG * DIM];    // fp16 plane (kPhix path)
__device__ __half g_W1Thi[(size_t)DIM * DIM];  // (64*W1)^T hi  [N,K]
__device__ __half g_W1Tlo[(size_t)DIM * DIM];
__device__ __half g_W3Thi[(size_t)DIM * DIM];
__device__ __half g_W3Tlo[(size_t)DIM * DIM];
__device__ float g_aF[DIM], g_cF[DIM], g_aG[DIM], g_cG[DIM];

// ---------------------------------------------------------------------------
// Helpers (base sm_103 target only — NO tcgen05 / arch-'a' features)
// ---------------------------------------------------------------------------
__device__ __forceinline__ uint32_t smem_u32(const void* p) {
    uint32_t a;
    asm("{ .reg .u64 t; cvta.to.shared.u64 t, %1; cvt.u32.u64 %0, t; }" : "=r"(a) : "l"(p));
    return a;
}

__device__ __forceinline__ void cp16(uint32_t saddr, const void* gptr) {
    asm volatile("cp.async.cg.shared.global [%0], [%1], 16;" :: "r"(saddr), "l"(gptr));
}
#define CP_COMMIT() asm volatile("cp.async.commit_group;" ::: "memory")
#define CP_WAIT(n)  asm volatile("cp.async.wait_group %0;" :: "n"(n) : "memory")

__device__ __forceinline__ void ldsm4(uint32_t* r, uint32_t addr) {
    asm volatile("ldmatrix.sync.aligned.m8n8.x4.shared.b16 {%0,%1,%2,%3}, [%4];"
                 : "=r"(r[0]), "=r"(r[1]), "=r"(r[2]), "=r"(r[3]) : "r"(addr));
}

__device__ __forceinline__ void mma_f16(float* d, const uint32_t* a, const uint32_t* b) {
    asm volatile(
        "mma.sync.aligned.m16n8k16.row.col.f32.f16.f16.f32 "
        "{%0,%1,%2,%3}, {%4,%5,%6,%7}, {%8,%9}, {%0,%1,%2,%3};"
        : "+f"(d[0]), "+f"(d[1]), "+f"(d[2]), "+f"(d[3])
        : "r"(a[0]), "r"(a[1]), "r"(a[2]), "r"(a[3]), "r"(b[0]), "r"(b[1]));
}

// pack 4 floats into 4 fp16 (uint2)
__device__ __forceinline__ uint2 quad_h(float s0, float s1, float s2, float s3) {
    __half2 h01 = __floats2half2_rn(s0, s1);
    __half2 h23 = __floats2half2_rn(s2, s3);
    uint2 r;
    r.x = *(uint32_t*)&h01;
    r.y = *(uint32_t*)&h23;
    return r;
}

// ---------------------------------------------------------------------------
// BN coefficient precompute
// ---------------------------------------------------------------------------
__global__ void bncoef_kernel(const float* __restrict__ g1, const float* __restrict__ be1,
                              const float* __restrict__ m1, const float* __restrict__ v1,
                              const float* __restrict__ g3, const float* __restrict__ be3,
                              const float* __restrict__ m3, const float* __restrict__ v3)
{
    int k = blockIdx.x * blockDim.x + threadIdx.x;
    if (k < DIM) {
        float aF = g1[k] * rsqrtf(v1[k] + 1e-3f);
        g_aF[k] = aF;  g_cF[k] = be1[k] - aF * m1[k];
        float aG = g3[k] * rsqrtf(v3[k] + 1e-3f);
        g_aG[k] = aG;  g_cG[k] = be3[k] - aG * m3[k];
    }
}

// ---------------------------------------------------------------------------
// Weight prep: W [K,N] -> (64*W)^T [N,K] split into fp16 hi/lo planes
// ---------------------------------------------------------------------------
__global__ void wprep_kernel(const float* __restrict__ W, __half* __restrict__ Thi,
                             __half* __restrict__ Tlo)
{
    __shared__ float t[32][33];
    int bn = blockIdx.x * 32;
    int bk = blockIdx.y * 32;
    int tx = threadIdx.x, ty = threadIdx.y;   // 32 x 8
    #pragma unroll
    for (int i = 0; i < 32; i += 8)
        t[ty + i][tx] = W[(size_t)(bk + ty + i) * DIM + bn + tx];
    __syncthreads();
    #pragma unroll
    for (int i = 0; i < 32; i += 8) {
        float v = t[tx][ty + i] * WSCALE;
        size_t o = (size_t)(bn + ty + i) * DIM + bk + tx;
        __half h = __float2half_rn(v);
        __half l = __float2half_rn(v - __half2float(h));
        Thi[o] = h;
        Tlo[o] = l;
    }
}

// ---------------------------------------------------------------------------
// xprep: one pass over x -> {S0 copy, S5 slice, u1, u2, fp16 BN_F(u2) plane}
// (R12-proven)
// ---------------------------------------------------------------------------
__global__ void xprep_kernel(const float* __restrict__ x, float* __restrict__ dst,
                             float* __restrict__ dsl,
                             float* __restrict__ u1, float* __restrict__ u2,
                             const float* __restrict__ aC, const float* __restrict__ cC,
                             __half* __restrict__ hi)
{
    size_t q = (size_t)blockIdx.x * blockDim.x + threadIdx.x;
    if (q >= (size_t)NIMG * DIM / 4) return;
    size_t idx = q * 4;
    int n = (int)(idx >> 11);
    int i = (int)((idx >> 5) & 63);
    int j0 = (int)(idx & 31);
    int p = i & 1;
    size_t xoff = ((size_t)n << 12) + ((size_t)i << 6) + (j0 << 1);
    float4 a = *(const float4*)(x + xoff);
    float4 b = *(const float4*)(x + xoff + 4);
    *(float4*)(dst + xoff) = a;
    *(float4*)(dst + xoff + 4) = b;
    int s = n % STD;
    if (s >= 1) {
        int cc = n / STD;
        size_t so = ((size_t)(cc * 11 + s - 1) << 12) + ((size_t)i << 6) + (j0 << 1);
        *(float4*)(dsl + so) = a;
        *(float4*)(dsl + so + 4) = b;
    }
    float4 f1, f2;
    if (p == 0) { f1 = make_float4(a.x, a.z, b.x, b.z); f2 = make_float4(a.y, a.w, b.y, b.w); }
    else        { f1 = make_float4(a.y, a.w, b.y, b.w); f2 = make_float4(a.x, a.z, b.x, b.z); }
    *(float4*)(u1 + idx) = f1;
    *(float4*)(u2 + idx) = f2;
    int k = (int)(idx & 2047);
    float4 av = *(const float4*)(aC + k);
    float4 cv = *(const float4*)(cC + k);
    *(uint2*)(hi + idx) = quad_h(av.x * f2.x + cv.x, av.y * f2.y + cv.y,
                                 av.z * f2.z + cv.z, av.w * f2.w + cv.w);
}

// ---------------------------------------------------------------------------
// mixsplit (R12-proven)
// ---------------------------------------------------------------------------
__global__ void mixsplit_kernel(const float* __restrict__ v1b, const float* __restrict__ w2b,
                                float* __restrict__ y, float* __restrict__ ysl,
                                float* __restrict__ u1o, float* __restrict__ u2o,
                                const float* __restrict__ aC, const float* __restrict__ cC,
                                __half* __restrict__ hi)
{
    size_t q = (size_t)blockIdx.x * blockDim.x + threadIdx.x;
    if (q >= (size_t)NIMG * DIM / 4) return;
    size_t idx = q * 4;
    int n = (int)(idx >> 11);
    int i = (int)((idx >> 5) & 63);
    int j0 = (int)(idx & 31);
    int p = i & 1;
    const float* v1 = v1b + ((size_t)n << 11) + ((size_t)i << 5);
    const float* w2 = w2b + ((size_t)n << 11) + ((size_t)i << 5);
    float u1[4], u2[4];
    if (p == 0) {
        float4 a = *(const float4*)(v1 + j0);
        float4 b = *(const float4*)(w2 + j0);
        u1[0] = a.x; u1[1] = a.y; u1[2] = a.z; u1[3] = a.w;
        u2[0] = b.x; u2[1] = b.y; u2[2] = b.z; u2[3] = b.w;
    } else {
        #pragma unroll
        for (int t = 0; t < 4; t++) {
            u1[t] = v1[(j0 + t + 1) & 31];
            u2[t] = w2[(j0 + t + 31) & 31];
        }
    }
    *(float4*)(u1o + idx) = make_float4(u1[0], u1[1], u1[2], u1[3]);
    *(float4*)(u2o + idx) = make_float4(u2[0], u2[1], u2[2], u2[3]);
    int k = (int)(idx & 2047);
    float4 av = *(const float4*)(aC + k);
    float4 cv = *(const float4*)(cC + k);
    *(uint2*)(hi + idx) = quad_h(av.x * u1[0] + cv.x, av.y * u1[1] + cv.y,
                                 av.z * u1[2] + cv.z, av.w * u1[3] + cv.w);
    float4 y0, y1;
    if (p == 0) {
        y0 = make_float4(u1[0], u2[0], u1[1], u2[1]);
        y1 = make_float4(u1[2], u2[2], u1[3], u2[3]);
    } else {
        y0 = make_float4(u2[0], u1[0], u2[1], u1[1]);
        y1 = make_float4(u2[2], u1[2], u2[3], u1[3]);
    }
    size_t yoff = ((size_t)n << 12) + ((size_t)i << 6) + (j0 << 1);
    *(float4*)(y + yoff) = y0;
    *(float4*)(y + yoff + 4) = y1;
    if (ysl) {
        int s = n % STD;
        if (s >= 1) {
            int cc = n / STD;
            size_t so = ((size_t)(cc * 11 + s - 1) << 12) + ((size_t)i << 6) + (j0 << 1);
            *(float4*)(ysl + so) = y0;
            *(float4*)(ysl + so + 4) = y1;
        }
    }
}

// ---------------------------------------------------------------------------
// Koopman step + fused split / fp16 BN-quant of the result. (R12-proven)
// ---------------------------------------------------------------------------
__global__ void __launch_bounds__(256)
koop_kernel(const float* __restrict__ phi, const float* __restrict__ kop,
            float* __restrict__ outk,
            float* __restrict__ u1o, float* __restrict__ u2o,
            const float* __restrict__ aC, const float* __restrict__ cC,
            __half* __restrict__ hi)
{
    __shared__ float sk[64 * 64];
    __shared__ float si[64 * 68];
    int m = blockIdx.x;
    int nprime = m / STD, s = m % STD;
    int q = nprime >> 2, b = nprime & 3;
    int nin = b * 64 + q;
    const float* src = phi + (size_t)(nin * STD + s) * IMGE;
    float* dst = outk + (size_t)m * IMGE;
    int t = threadIdx.x;

    #pragma unroll
    for (int e = t * 4; e < IMGE; e += 1024)
        *(float4*)(sk + e) = *(const float4*)(kop + e);
    #pragma unroll
    for (int e = t; e < IMGE; e += 256) {
        int i = e >> 6, j = e & 63;
        si[j * 68 + i] = src[e];
    }
    __syncthreads();

    int tr = t >> 4, tc = t & 15;
    float acc[4][4];
    #pragma unroll
    for (int a = 0; a < 4; a++)
        #pragma unroll
        for (int bb = 0; bb < 4; bb++) acc[a][bb] = 0.f;

    const float* siP = si + tr * 4;
    const float* skP = sk + tc * 4;
    #pragma unroll 4
    for (int j = 0; j < 64; j++) {
        float4 av = *(const float4*)(siP + j * 68);
        float4 bv = *(const float4*)(skP + j * 64);
        acc[0][0] += av.x * bv.x; acc[0][1] += av.x * bv.y;
        acc[0][2] += av.x * bv.z; acc[0][3] += av.x * bv.w;
        acc[1][0] += av.y * bv.x; acc[1][1] += av.y * bv.y;
        acc[1][2] += av.y * bv.z; acc[1][3] += av.y * bv.w;
        acc[2][0] += av.z * bv.x; acc[2][1] += av.z * bv.y;
        acc[2][2] += av.z * bv.z; acc[2][3] += av.z * bv.w;
        acc[3][0] += av.w * bv.x; acc[3][1] += av.w * bv.y;
        acc[3][2] += av.w * bv.z; acc[3][3] += av.w * bv.w;
    }
    __syncthreads();
    float* sy = si;                   // reuse as y rows, pitch 66
    #pragma unroll
    for (int dr = 0; dr < 4; dr++) {
        int row = tr * 4 + dr;
        float4 o = make_float4(acc[dr][0], acc[dr][1], acc[dr][2], acc[dr][3]);
        *(float4*)(dst + row * 64 + tc * 4) = o;
        sy[row * 66 + tc * 4 + 0] = o.x;
        sy[row * 66 + tc * 4 + 1] = o.y;
        sy[row * 66 + tc * 4 + 2] = o.z;
        sy[row * 66 + tc * 4 + 3] = o.w;
    }
    __syncthreads();

    #pragma unroll
    for (int e8 = 0; e8 < 8; e8++) {
        int e = t + e8 * 256;
        int i = e >> 5, j = e & 31, p = i & 1;
        float uu1 = sy[i * 66 + 2 * j + p];
        float uu2 = sy[i * 66 + 2 * j + 1 - p];
        size_t go = (size_t)m * DIM + e;
        u1o[go] = uu1;
        u2o[go] = uu2;
        hi[go] = __float2half_rn(aC[e] * uu1 + cC[e]);
    }
}

// ---------------------------------------------------------------------------
// FP16 2-term GEMM (m16n8k16 + ldmatrix) — R12 mainloop, batched halves.
//   res[m,n] = base[m,n] + sign*( (1/64)*sum_k A[m,k]*(Whi+Wlo)[n,k] + bias[n] )
// halves=1: grid.y = 24;  halves=2: grid.y = 48, blockIdx.y>=24 selects the
//   second pointer set (Ah2/base2/outp2/eHi2/u2mix2/ymix2). Tiles never
//   straddle halves (GM=128 divides 3072).
// fuse=0: write res to outp; emit=1 also writes fp16 BN(res) plane eHi.
// fuse=1: res = u1 (v1-role); mix with u2mix (w2-role) -> ymix. No raw write.
// ---------------------------------------------------------------------------
#define GM 128
#define GN 128
#define BK 32
#define NT_K (DIM / BK)            // 64
#define PITCHB 80
#define PLANE_B (128 * PITCHB)     // 10240
#define STAGE_B (3 * PLANE_B)      // 30720
#define STAGES 3
#define SM_TOTAL (STAGES * STAGE_B)   // 92160
#define MIXP 132                   // fused-mix smem pitch (floats)
#define YT  (NIMG / GM)            // 24 y-tiles per half

__global__ void __launch_bounds__(256, 2)
gemm_tc_kernel(const __half* Ah, const __half* Ah2,
               const __half* __restrict__ Whi, const __half* __restrict__ Wlo,
               const float* __restrict__ bias,
               const float* base, const float* base2,
               float* outp, float* outp2, float sign,
               const float* __restrict__ aN, const float* __restrict__ cN,
               __half* eHi, __half* eHi2, int emit,
               const float* u2mix, const float* u2mix2,
               float* ymix, float* ymix2, int fuse)
{
    extern __shared__ char smem[];
    uint32_t sb = smem_u32(smem);
    const int tid  = threadIdx.x;
    const int wid  = tid >> 5;
    const int lane = tid & 31;
    const int gid  = lane >> 2;
    const int tig  = lane & 3;
    const int warpM = wid >> 2;
    const int warpN = wid & 3;

    int by = blockIdx.y;
    if (by >= YT) {            // second half
        by -= YT;
        Ah = Ah2; base = base2; outp = outp2; eHi = eHi2;
        u2mix = u2mix2; ymix = ymix2;
    }
    const int m0 = by * GM;
    const int n0 = blockIdx.x * GN;

    float acc[4][4][4];
    #pragma unroll
    for (int i = 0; i < 4; i++)
        #pragma unroll
        for (int j = 0; j < 4; j++)
            #pragma unroll
            for (int c = 0; c < 4; c++) acc[i][j][c] = 0.f;

    const int t8 = lane >> 3;
    const int r8 = lane & 7;
    const uint32_t aoff = (uint32_t)((warpM * 64 + (t8 & 1) * 8 + r8) * PITCHB + (t8 >> 1) * 16);
    const uint32_t boff = (uint32_t)(PLANE_B +
                          (warpN * 32 + (t8 >> 1) * 8 + r8) * PITCHB + (t8 & 1) * 16);

    auto load_tile = [&](int s, int t) {
        const int k0 = t * BK;
        uint32_t stage = sb + (uint32_t)(s * STAGE_B);
        #pragma unroll
        for (int j = 0; j < 6; j++) {
            int c = tid + j * 256;
            int pl = c >> 9;                 // 0=A, 1=Whi, 2=Wlo
            int cc = c & 511;
            int row = cc >> 2;
            int c4  = cc & 3;
            const __half* g;
            if (pl == 0)      g = Ah  + (size_t)(m0 + row) * DIM + k0 + c4 * 8;
            else if (pl == 1) g = Whi + (size_t)(n0 + row) * DIM + k0 + c4 * 8;
            else              g = Wlo + (size_t)(n0 + row) * DIM + k0 + c4 * 8;
            cp16(stage + (uint32_t)(pl * PLANE_B + row * PITCHB + c4 * 16), g);
        }
    };

    #pragma unroll
    for (int s = 0; s < STAGES; s++) {
        load_tile(s, s);
        CP_COMMIT();
    }

    for (int t = 0; t < NT_K; t++) {
        CP_WAIT(2);
        __syncthreads();
        uint32_t stg = sb + (uint32_t)((t % STAGES) * STAGE_B);
        uint32_t aB = stg + aoff;
        uint32_t bB = stg + boff;

        #pragma unroll
        for (int kk = 0; kk < BK; kk += 16) {
            uint32_t Af[4][4], Bh[4][2], Bl[4][2];
            #pragma unroll
            for (int mi = 0; mi < 4; mi++)
                ldsm4(Af[mi], aB + (uint32_t)(mi * 16 * PITCHB + kk * 2));
            #pragma unroll
            for (int nip = 0; nip < 2; nip++) {
                uint32_t b = bB + (uint32_t)(nip * 16 * PITCHB + kk * 2);
                uint32_t th[4], tl[4];
                ldsm4(th, b);
                ldsm4(tl, b + PLANE_B);
                Bh[nip * 2][0] = th[0]; Bh[nip * 2][1] = th[1];
                Bh[nip * 2 + 1][0] = th[2]; Bh[nip * 2 + 1][1] = th[3];
                Bl[nip * 2][0] = tl[0]; Bl[nip * 2][1] = tl[1];
                Bl[nip * 2 + 1][0] = tl[2]; Bl[nip * 2 + 1][1] = tl[3];
            }
            #pragma unroll
            for (int mi = 0; mi < 4; mi++)
                #pragma unroll
                for (int ni = 0; ni < 4; ni++) {
                    mma_f16(acc[mi][ni], Af[mi], Bh[ni]);
                    mma_f16(acc[mi][ni], Af[mi], Bl[ni]);
                }
        }
        __syncthreads();
        if (t + STAGES < NT_K) load_tile(t % STAGES, t + STAGES);
        CP_COMMIT();
    }

    if (!fuse) {
        #pragma unroll
        for (int mi = 0; mi < 4; mi++) {
            #pragma unroll
            for (int half = 0; half < 2; half++) {
                size_t m = (size_t)(m0 + warpM * 64 + mi * 16 + gid + half * 8);
                #pragma unroll
                for (int ni = 0; ni < 4; ni++) {
                    int n = n0 + warpN * 32 + ni * 8 + 2 * tig;
                    float r0 = acc[mi][ni][half * 2 + 0] * WSCALE_INV;
                    float r1 = acc[mi][ni][half * 2 + 1] * WSCALE_INV;
                    float2 bs = *(const float2*)(bias + n);
                    float2 bb = *(const float2*)(base + m * DIM + n);
                    float2 o;
                    o.x = bb.x + sign * (r0 + bs.x);
                    o.y = bb.y + sign * (r1 + bs.y);
                    *(float2*)(outp + m * DIM + n) = o;
                    if (emit) {
                        float2 a2 = *(const float2*)(aN + n);
                        float2 c2 = *(const float2*)(cN + n);
                        __half2 h2 = __floats2half2_rn(a2.x * o.x + c2.x, a2.y * o.y + c2.y);
                        *(__half2*)(eHi + m * DIM + n) = h2;
                    }
                }
            }
        }
    } else {
        // ---- fused-mix epilogue (R12-proven) ----
        float* su1 = (float*)smem;                 // [128][MIXP]
        float* su2 = su1 + 128 * MIXP;             // [32][MIXP]
        #pragma unroll
        for (int mi = 0; mi < 4; mi++) {
            #pragma unroll
            for (int half = 0; half < 2; half++) {
                int ml = warpM * 64 + mi * 16 + gid + half * 8;
                size_t m = (size_t)(m0 + ml);
                #pragma unroll
                for (int ni = 0; ni < 4; ni++) {
                    int nl = warpN * 32 + ni * 8 + 2 * tig;
                    int n = n0 + nl;
                    float r0 = acc[mi][ni][half * 2 + 0] * WSCALE_INV;
                    float r1 = acc[mi][ni][half * 2 + 1] * WSCALE_INV;
                    float2 bs = *(const float2*)(bias + n);
                    float2 bb = *(const float2*)(base + m * DIM + n);
                    float2 o;
                    o.x = bb.x + sign * (r0 + bs.x);
                    o.y = bb.y + sign * (r1 + bs.y);
                    *(float2*)(su1 + ml * MIXP + nl) = o;
                }
            }
        }
        __syncthreads();

        const int i0 = n0 >> 5;
        #pragma unroll 1
        for (int chunk = 0; chunk < 4; chunk++) {
            #pragma unroll
            for (int l = tid; l < 1024; l += 256) {
                int mm = l >> 5;
                int f4 = l & 31;
                float4 v = *(const float4*)(u2mix +
                    (size_t)(m0 + chunk * 32 + mm) * DIM + n0 + f4 * 4);
                *(float4*)(su2 + mm * MIXP + f4 * 4) = v;
            }
            __syncthreads();
            #pragma unroll
            for (int pp = 0; pp < 8; pp++) {
                int mm = pp * 4 + (tid >> 6);
                int qq = tid & 63;
                int il = qq >> 4;
                int c0 = (qq & 15) * 4;
                int ig = i0 + il;
                const float* r1 = su1 + (chunk * 32 + mm) * MIXP + il * 32;
                const float* r2 = su2 + mm * MIXP + il * 32;
                int h = c0 >> 1;
                float4 o;
                if ((ig & 1) == 0) {
                    o.x = r1[h];     o.y = r2[h];
                    o.z = r1[h + 1]; o.w = r2[h + 1];
                } else {
                    o.x = r2[(h + 31) & 31];
                    o.y = r1[(h + 1) & 31];
                    o.z = r2[h];
                    o.w = r1[(h + 2) & 31];
                }
                *(float4*)(ymix + (size_t)(m0 + chunk * 32 + mm) * IMGE + ig * 64 + c0) = o;
            }
            __syncthreads();
        }
    }
}

// ---------------------------------------------------------------------------
extern "C" void kernel_launch(void* const* d_in, const int* in_sizes, int n_in,
                              void* d_out, int out_size)
{
    const float* x   = (const float*)d_in[0];
    const float* W1  = (const float*)d_in[2];
    const float* b1  = (const float*)d_in[3];
    const float* g1  = (const float*)d_in[4];
    const float* be1 = (const float*)d_in[5];
    const float* m1  = (const float*)d_in[6];
    const float* v1  = (const float*)d_in[7];
    const float* W3  = (const float*)d_in[8];
    const float* b3  = (const float*)d_in[9];
    const float* g3  = (const float*)d_in[10];
    const float* be3 = (const float*)d_in[11];
    const float* m3  = (const float*)d_in[12];
    const float* v3  = (const float*)d_in[13];
    const float* kop = (const float*)d_in[14];
    float* out = (float*)d_out;

    float *A, *B, *C, *D, *aF, *cF, *aG, *cG;
    __half *H0, *H1, *H2, *H3, *W1h, *W1l, *W3h, *W3l;
    cudaGetSymbolAddress((void**)&A,  g_A);
    cudaGetSymbolAddress((void**)&B,  g_B);
    cudaGetSymbolAddress((void**)&C,  g_C);
    cudaGetSymbolAddress((void**)&D,  g_D);
    cudaGetSymbolAddress((void**)&H0, g_H0);
    cudaGetSymbolAddress((void**)&H1, g_H1);
    cudaGetSymbolAddress((void**)&H2, g_H2);
    cudaGetSymbolAddress((void**)&H3, g_H3);
    cudaGetSymbolAddress((void**)&W1h, g_W1Thi);
    cudaGetSymbolAddress((void**)&W1l, g_W1Tlo);
    cudaGetSymbolAddress((void**)&W3h, g_W3Thi);
    cudaGetSymbolAddress((void**)&W3l, g_W3Tlo);
    cudaGetSymbolAddress((void**)&aF, g_aF);
    cudaGetSymbolAddress((void**)&cF, g_cF);
    cudaGetSymbolAddress((void**)&aG, g_aG);
    cudaGetSymbolAddress((void**)&cG, g_cG);

    static int smem_set = 0;
    if (!smem_set) {
        cudaFuncSetAttribute(gemm_tc_kernel, cudaFuncAttributeMaxDynamicSharedMemorySize,
                             SM_TOTAL);
        smem_set = 1;
    }

    dim3 g1grid(DIM / GN, YT);                 // (16, 24)  single half
    dim3 g2grid(DIM / GN, 2 * YT);             // (16, 48)  both halves
    const int UQ_BLKS = (int)(((size_t)NIMG * DIM / 4 + 255) / 256);
    dim3 wgrid(DIM / 32, DIM / 32), wblk(32, 8);

    bncoef_kernel<<<8, 256>>>(g1, be1, m1, v1, g3, be3, m3, v3);
    wprep_kernel<<<wgrid, wblk>>>(W1, W1h, W1l);
    wprep_kernel<<<wgrid, wblk>>>(W3, W3h, W3l);

    // ---- x prep: S0, S5, u1(A), u2(B), fp16 BN_F(u2) plane ----
    xprep_kernel<<<UQ_BLKS, 256>>>(x, out + S0, out + S5, A, B, aF, cF, H0);

    // ---- Encoder ----
    // A = v1 = u1 + F(u2), emit H1 = BN_G(v1)
    gemm_tc_kernel<<<g1grid, 256, SM_TOTAL>>>(H0, nullptr, W1h, W1l, b1,
                                              A, nullptr, A, nullptr, +1.0f,
                                              aG, cG, H1, nullptr, 1,
                                              nullptr, nullptr, nullptr, nullptr, 0);
    // B = w2 = u2 + G(v1)
    gemm_tc_kernel<<<g1grid, 256, SM_TOTAL>>>(H1, nullptr, W3h, W3l, b3,
                                              B, nullptr, B, nullptr, +1.0f,
                                              aF, cF, H0, nullptr, 0,
                                              nullptr, nullptr, nullptr, nullptr, 0);
    // phiX + slice + decoder split (C=w1, D=w2rolled) + H0 = fp16 BN_G(w1)
    mixsplit_kernel<<<UQ_BLKS, 256>>>(A, B, out + S1, out + S6, C, D, aG, cG, H0);

    // ---- Koopman (kPhix split: A=w1', B=w2'rolled, H2 = fp16 BN_G(w1')) ----
    koop_kernel<<<NIMG, 256>>>(out + S1, kop, out + S3, A, B, aG, cG, H2);

    // ---- Merged decoders: G-GEMMs (both halves, one launch) ----
    // half0: D = v2  = D - G(w1),  emit H1 = BN_F(v2)
    // half1: B = v2' = B - G(w1'), emit H3 = BN_F(v2')
    gemm_tc_kernel<<<g2grid, 256, SM_TOTAL>>>(H0, H2, W3h, W3l, b3,
                                              D, B, D, B, -1.0f,
                                              aF, cF, H1, H3, 1,
                                              nullptr, nullptr, nullptr, nullptr, 0);
    // ---- Merged decoders: F-GEMMs + fused mix (both halves, one launch) ----
    // half0: u1  = w1  - F(v2),  S2 = mix(u1, D)
    // half1: u1' = w1' - F(v2'), S4 = mix(u1', B)
    gemm_tc_kernel<<<g2grid, 256, SM_TOTAL>>>(H1, H3, W1h, W1l, b1,
                                              C, A, nullptr, nullptr, -1.0f,
                                              nullptr, nullptr, nullptr, nullptr, 0,
                                              D, B, out + S2, out + S4, 1);
}

// round 17
// speedup vs baseline: 1.4639x; 1.4639x over previous
#include <cuda_runtime.h>
#include <cuda_bf16.h>
#include <cuda_fp16.h>
#include <cstdint>

// ---------------------------------------------------------------------------
// Problem constants
// ---------------------------------------------------------------------------
#define CCN   256
#define STD   12
#define FS    64
#define HALF  32
#define NIMG  (CCN*STD)          // 3072
#define DIM   2048               // FS*HALF
#define IMGE  (FS*FS)            // 4096

#define WSCALE     64.0f
#define WSCALE_INV 0.015625f

static const size_t T_FULL  = (size_t)NIMG * IMGE;
static const size_t T_SLICE = (size_t)CCN * 11 * IMGE;

// Output section offsets (floats)
static const size_t S0 = 0;                    // x
static const size_t S1 = S0 + T_FULL;          // phiX
static const size_t S2 = S1 + T_FULL;          // dephiPhiX
static const size_t S3 = S2 + T_FULL;          // kPhix
static const size_t S4 = S3 + T_FULL;          // dePhiKPhiX
static const size_t S5 = S4 + T_FULL;          // x[:,1:]
static const size_t S6 = S5 + T_SLICE;         // phiX[:,1:]

// ---------------------------------------------------------------------------
// Scratch (device globals — no runtime allocation allowed)
// ---------------------------------------------------------------------------
__device__ float  g_A [(size_t)NIMG * DIM];
__device__ float  g_B [(size_t)NIMG * DIM];
__device__ float  g_C [(size_t)NIMG * DIM];
__device__ float  g_D [(size_t)NIMG * DIM];
__device__ __half g_H0[(size_t)NIMG * DIM];    // fp16 activation plane (ping)
__device__ __half g_H1[(size_t)NIMG * DIM];    // fp16 activation plane (pong)
__device__ __half g_W1T[(size_t)DIM * DIM];    // (64*W1)^T fp16 [N,K]
__device__ __half g_W3T[(size_t)DIM * DIM];    // (64*W3)^T fp16 [N,K]
__device__ float g_aF[DIM], g_cF[DIM], g_aG[DIM], g_cG[DIM];

// ---------------------------------------------------------------------------
// Helpers (base sm_103 target only — NO tcgen05 / arch-'a' features)
// ---------------------------------------------------------------------------
__device__ __forceinline__ uint32_t smem_u32(const void* p) {
    uint32_t a;
    asm("{ .reg .u64 t; cvta.to.shared.u64 t, %1; cvt.u32.u64 %0, t; }" : "=r"(a) : "l"(p));
    return a;
}

__device__ __forceinline__ void cp16(uint32_t saddr, const void* gptr) {
    asm volatile("cp.async.cg.shared.global [%0], [%1], 16;" :: "r"(saddr), "l"(gptr));
}
#define CP_COMMIT() asm volatile("cp.async.commit_group;" ::: "memory")
#define CP_WAIT(n)  asm volatile("cp.async.wait_group %0;" :: "n"(n) : "memory")

__device__ __forceinline__ void ldsm4(uint32_t* r, uint32_t addr) {
    asm volatile("ldmatrix.sync.aligned.m8n8.x4.shared.b16 {%0,%1,%2,%3}, [%4];"
                 : "=r"(r[0]), "=r"(r[1]), "=r"(r[2]), "=r"(r[3]) : "r"(addr));
}

__device__ __forceinline__ void mma_f16(float* d, const uint32_t* a, const uint32_t* b) {
    asm volatile(
        "mma.sync.aligned.m16n8k16.row.col.f32.f16.f16.f32 "
        "{%0,%1,%2,%3}, {%4,%5,%6,%7}, {%8,%9}, {%0,%1,%2,%3};"
        : "+f"(d[0]), "+f"(d[1]), "+f"(d[2]), "+f"(d[3])
        : "r"(a[0]), "r"(a[1]), "r"(a[2]), "r"(a[3]), "r"(b[0]), "r"(b[1]));
}

// pack 4 floats into 4 fp16 (uint2)
__device__ __forceinline__ uint2 quad_h(float s0, float s1, float s2, float s3) {
    __half2 h01 = __floats2half2_rn(s0, s1);
    __half2 h23 = __floats2half2_rn(s2, s3);
    uint2 r;
    r.x = *(uint32_t*)&h01;
    r.y = *(uint32_t*)&h23;
    return r;
}

// ---------------------------------------------------------------------------
// BN coefficient precompute
// ---------------------------------------------------------------------------
__global__ void bncoef_kernel(const float* __restrict__ g1, const float* __restrict__ be1,
                              const float* __restrict__ m1, const float* __restrict__ v1,
                              const float* __restrict__ g3, const float* __restrict__ be3,
                              const float* __restrict__ m3, const float* __restrict__ v3)
{
    int k = blockIdx.x * blockDim.x + threadIdx.x;
    if (k < DIM) {
        float aF = g1[k] * rsqrtf(v1[k] + 1e-3f);
        g_aF[k] = aF;  g_cF[k] = be1[k] - aF * m1[k];
        float aG = g3[k] * rsqrtf(v3[k] + 1e-3f);
        g_aG[k] = aG;  g_cG[k] = be3[k] - aG * m3[k];
    }
}

// ---------------------------------------------------------------------------
// Weight prep: W [K,N] -> (64*W)^T [N,K] single fp16 plane
// ---------------------------------------------------------------------------
__global__ void wprep_kernel(const float* __restrict__ W, __half* __restrict__ T)
{
    __shared__ float t[32][33];
    int bn = blockIdx.x * 32;
    int bk = blockIdx.y * 32;
    int tx = threadIdx.x, ty = threadIdx.y;   // 32 x 8
    #pragma unroll
    for (int i = 0; i < 32; i += 8)
        t[ty + i][tx] = W[(size_t)(bk + ty + i) * DIM + bn + tx];
    __syncthreads();
    #pragma unroll
    for (int i = 0; i < 32; i += 8) {
        float v = t[tx][ty + i] * WSCALE;
        T[(size_t)(bn + ty + i) * DIM + bk + tx] = __float2half_rn(v);
    }
}

// ---------------------------------------------------------------------------
// xprep: one pass over x -> {S0 copy, S5 slice, u1, u2, fp16 BN_F(u2) plane}
// (R12-proven)
// ---------------------------------------------------------------------------
__global__ void xprep_kernel(const float* __restrict__ x, float* __restrict__ dst,
                             float* __restrict__ dsl,
                             float* __restrict__ u1, float* __restrict__ u2,
                             const float* __restrict__ aC, const float* __restrict__ cC,
                             __half* __restrict__ hi)
{
    size_t q = (size_t)blockIdx.x * blockDim.x + threadIdx.x;
    if (q >= (size_t)NIMG * DIM / 4) return;
    size_t idx = q * 4;
    int n = (int)(idx >> 11);
    int i = (int)((idx >> 5) & 63);
    int j0 = (int)(idx & 31);
    int p = i & 1;
    size_t xoff = ((size_t)n << 12) + ((size_t)i << 6) + (j0 << 1);
    float4 a = *(const float4*)(x + xoff);
    float4 b = *(const float4*)(x + xoff + 4);
    *(float4*)(dst + xoff) = a;
    *(float4*)(dst + xoff + 4) = b;
    int s = n % STD;
    if (s >= 1) {
        int cc = n / STD;
        size_t so = ((size_t)(cc * 11 + s - 1) << 12) + ((size_t)i << 6) + (j0 << 1);
        *(float4*)(dsl + so) = a;
        *(float4*)(dsl + so + 4) = b;
    }
    float4 f1, f2;
    if (p == 0) { f1 = make_float4(a.x, a.z, b.x, b.z); f2 = make_float4(a.y, a.w, b.y, b.w); }
    else        { f1 = make_float4(a.y, a.w, b.y, b.w); f2 = make_float4(a.x, a.z, b.x, b.z); }
    *(float4*)(u1 + idx) = f1;
    *(float4*)(u2 + idx) = f2;
    int k = (int)(idx & 2047);
    float4 av = *(const float4*)(aC + k);
    float4 cv = *(const float4*)(cC + k);
    *(uint2*)(hi + idx) = quad_h(av.x * f2.x + cv.x, av.y * f2.y + cv.y,
                                 av.z * f2.z + cv.z, av.w * f2.w + cv.w);
}

// ---------------------------------------------------------------------------
// mixsplit (R12-proven)
// ---------------------------------------------------------------------------
__global__ void mixsplit_kernel(const float* __restrict__ v1b, const float* __restrict__ w2b,
                                float* __restrict__ y, float* __restrict__ ysl,
                                float* __restrict__ u1o, float* __restrict__ u2o,
                                const float* __restrict__ aC, const float* __restrict__ cC,
                                __half* __restrict__ hi)
{
    size_t q = (size_t)blockIdx.x * blockDim.x + threadIdx.x;
    if (q >= (size_t)NIMG * DIM / 4) return;
    size_t idx = q * 4;
    int n = (int)(idx >> 11);
    int i = (int)((idx >> 5) & 63);
    int j0 = (int)(idx & 31);
    int p = i & 1;
    const float* v1 = v1b + ((size_t)n << 11) + ((size_t)i << 5);
    const float* w2 = w2b + ((size_t)n << 11) + ((size_t)i << 5);
    float u1[4], u2[4];
    if (p == 0) {
        float4 a = *(const float4*)(v1 + j0);
        float4 b = *(const float4*)(w2 + j0);
        u1[0] = a.x; u1[1] = a.y; u1[2] = a.z; u1[3] = a.w;
        u2[0] = b.x; u2[1] = b.y; u2[2] = b.z; u2[3] = b.w;
    } else {
        #pragma unroll
        for (int t = 0; t < 4; t++) {
            u1[t] = v1[(j0 + t + 1) & 31];
            u2[t] = w2[(j0 + t + 31) & 31];
        }
    }
    *(float4*)(u1o + idx) = make_float4(u1[0], u1[1], u1[2], u1[3]);
    *(float4*)(u2o + idx) = make_float4(u2[0], u2[1], u2[2], u2[3]);
    int k = (int)(idx & 2047);
    float4 av = *(const float4*)(aC + k);
    float4 cv = *(const float4*)(cC + k);
    *(uint2*)(hi + idx) = quad_h(av.x * u1[0] + cv.x, av.y * u1[1] + cv.y,
                                 av.z * u1[2] + cv.z, av.w * u1[3] + cv.w);
    float4 y0, y1;
    if (p == 0) {
        y0 = make_float4(u1[0], u2[0], u1[1], u2[1]);
        y1 = make_float4(u1[2], u2[2], u1[3], u2[3]);
    } else {
        y0 = make_float4(u2[0], u1[0], u2[1], u1[1]);
        y1 = make_float4(u2[2], u1[2], u2[3], u1[3]);
    }
    size_t yoff = ((size_t)n << 12) + ((size_t)i << 6) + (j0 << 1);
    *(float4*)(y + yoff) = y0;
    *(float4*)(y + yoff + 4) = y1;
    if (ysl) {
        int s = n % STD;
        if (s >= 1) {
            int cc = n / STD;
            size_t so = ((size_t)(cc * 11 + s - 1) << 12) + ((size_t)i << 6) + (j0 << 1);
            *(float4*)(ysl + so) = y0;
            *(float4*)(ysl + so + 4) = y1;
        }
    }
}

// ---------------------------------------------------------------------------
// Koopman step + fused split / fp16 BN-quant of the result. (R12-proven)
// ---------------------------------------------------------------------------
__global__ void __launch_bounds__(256)
koop_kernel(const float* __restrict__ phi, const float* __restrict__ kop,
            float* __restrict__ outk,
            float* __restrict__ u1o, float* __restrict__ u2o,
            const float* __restrict__ aC, const float* __restrict__ cC,
            __half* __restrict__ hi)
{
    __shared__ float sk[64 * 64];
    __shared__ float si[64 * 68];
    int m = blockIdx.x;
    int nprime = m / STD, s = m % STD;
    int q = nprime >> 2, b = nprime & 3;
    int nin = b * 64 + q;
    const float* src = phi + (size_t)(nin * STD + s) * IMGE;
    float* dst = outk + (size_t)m * IMGE;
    int t = threadIdx.x;

    #pragma unroll
    for (int e = t * 4; e < IMGE; e += 1024)
        *(float4*)(sk + e) = *(const float4*)(kop + e);
    #pragma unroll
    for (int e = t; e < IMGE; e += 256) {
        int i = e >> 6, j = e & 63;
        si[j * 68 + i] = src[e];
    }
    __syncthreads();

    int tr = t >> 4, tc = t & 15;
    float acc[4][4];
    #pragma unroll
    for (int a = 0; a < 4; a++)
        #pragma unroll
        for (int bb = 0; bb < 4; bb++) acc[a][bb] = 0.f;

    const float* siP = si + tr * 4;
    const float* skP = sk + tc * 4;
    #pragma unroll 4
    for (int j = 0; j < 64; j++) {
        float4 av = *(const float4*)(siP + j * 68);
        float4 bv = *(const float4*)(skP + j * 64);
        acc[0][0] += av.x * bv.x; acc[0][1] += av.x * bv.y;
        acc[0][2] += av.x * bv.z; acc[0][3] += av.x * bv.w;
        acc[1][0] += av.y * bv.x; acc[1][1] += av.y * bv.y;
        acc[1][2] += av.y * bv.z; acc[1][3] += av.y * bv.w;
        acc[2][0] += av.z * bv.x; acc[2][1] += av.z * bv.y;
        acc[2][2] += av.z * bv.z; acc[2][3] += av.z * bv.w;
        acc[3][0] += av.w * bv.x; acc[3][1] += av.w * bv.y;
        acc[3][2] += av.w * bv.z; acc[3][3] += av.w * bv.w;
    }
    __syncthreads();
    float* sy = si;                   // reuse as y rows, pitch 66
    #pragma unroll
    for (int dr = 0; dr < 4; dr++) {
        int row = tr * 4 + dr;
        float4 o = make_float4(acc[dr][0], acc[dr][1], acc[dr][2], acc[dr][3]);
        *(float4*)(dst + row * 64 + tc * 4) = o;
        sy[row * 66 + tc * 4 + 0] = o.x;
        sy[row * 66 + tc * 4 + 1] = o.y;
        sy[row * 66 + tc * 4 + 2] = o.z;
        sy[row * 66 + tc * 4 + 3] = o.w;
    }
    __syncthreads();

    #pragma unroll
    for (int e8 = 0; e8 < 8; e8++) {
        int e = t + e8 * 256;
        int i = e >> 5, j = e & 31, p = i & 1;
        float uu1 = sy[i * 66 + 2 * j + p];
        float uu2 = sy[i * 66 + 2 * j + 1 - p];
        size_t go = (size_t)m * DIM + e;
        u1o[go] = uu1;
        u2o[go] = uu2;
        hi[go] = __float2half_rn(aC[e] * uu1 + cC[e]);
    }
}

// ---------------------------------------------------------------------------
// FP16 single-plane GEMM (m16n8k16 + ldmatrix) — R12 structure, 2 smem planes.
//   res[m,n] = base[m,n] + sign*( (1/64)*sum_k A[m,k]*W[n,k] + bias[n] )
// A: fp16 plane [M,K]; W: fp16 plane of (64*W)^T [N,K].
// fuse=0: write res to outp; emit=1 also writes fp16 BN(res) plane eHi.
// fuse=1: res = u1 (v1-role); mix with u2mix (w2-role) -> ymix. No raw write.
// CTA tile 128x128, BK=32, 8 warps (2x4), warp tile 64x32,
// 3-stage cp.async pipeline (20KB/stage). SM_TOTAL kept at 92160 so the
// fused-mix epilogue smem layout (84480 B) fits; still 2 CTAs per SM.
// ---------------------------------------------------------------------------
#define GM 128
#define GN 128
#define BK 32
#define NT_K (DIM / BK)            // 64
#define PITCHB 80
#define PLANE_B (128 * PITCHB)     // 10240
#define STAGE_B (2 * PLANE_B)      // 20480
#define STAGES 3
#define SM_TOTAL 92160             // >= max(3*STAGE_B, fused-mix layout)
#define MIXP 132                   // fused-mix smem pitch (floats)

__global__ void __launch_bounds__(256, 2)
gemm_tc_kernel(const __half* __restrict__ Ah, const __half* __restrict__ Wh,
               const float* __restrict__ bias, const float* base, float* outp, float sign,
               const float* __restrict__ aN, const float* __restrict__ cN,
               __half* eHi, int emit,
               const float* __restrict__ u2mix, float* __restrict__ ymix, int fuse)
{
    extern __shared__ char smem[];
    uint32_t sb = smem_u32(smem);
    const int tid  = threadIdx.x;
    const int wid  = tid >> 5;
    const int lane = tid & 31;
    const int gid  = lane >> 2;
    const int tig  = lane & 3;
    const int warpM = wid >> 2;
    const int warpN = wid & 3;
    const int m0 = blockIdx.y * GM;
    const int n0 = blockIdx.x * GN;

    float acc[4][4][4];
    #pragma unroll
    for (int i = 0; i < 4; i++)
        #pragma unroll
        for (int j = 0; j < 4; j++)
            #pragma unroll
            for (int c = 0; c < 4; c++) acc[i][j][c] = 0.f;

    const int t8 = lane >> 3;
    const int r8 = lane & 7;
    const uint32_t aoff = (uint32_t)((warpM * 64 + (t8 & 1) * 8 + r8) * PITCHB + (t8 >> 1) * 16);
    const uint32_t boff = (uint32_t)(PLANE_B +
                          (warpN * 32 + (t8 >> 1) * 8 + r8) * PITCHB + (t8 & 1) * 16);

    // loader: 2 planes x 512 chunks = 1024 chunks, 4 per thread
    auto load_tile = [&](int s, int t) {
        const int k0 = t * BK;
        uint32_t stage = sb + (uint32_t)(s * STAGE_B);
        #pragma unroll
        for (int j = 0; j < 4; j++) {
            int c = tid + j * 256;
            int pl = c >> 9;                 // 0=A, 1=W
            int cc = c & 511;
            int row = cc >> 2;
            int c4  = cc & 3;
            const __half* g;
            if (pl == 0) g = Ah + (size_t)(m0 + row) * DIM + k0 + c4 * 8;
            else         g = Wh + (size_t)(n0 + row) * DIM + k0 + c4 * 8;
            cp16(stage + (uint32_t)(pl * PLANE_B + row * PITCHB + c4 * 16), g);
        }
    };

    #pragma unroll
    for (int s = 0; s < STAGES; s++) {
        load_tile(s, s);
        CP_COMMIT();
    }

    for (int t = 0; t < NT_K; t++) {
        CP_WAIT(2);
        __syncthreads();
        uint32_t stg = sb + (uint32_t)((t % STAGES) * STAGE_B);
        uint32_t aB = stg + aoff;
        uint32_t bB = stg + boff;

        #pragma unroll
        for (int kk = 0; kk < BK; kk += 16) {
            uint32_t Af[4][4], Bf[4][2];
            #pragma unroll
            for (int mi = 0; mi < 4; mi++)
                ldsm4(Af[mi], aB + (uint32_t)(mi * 16 * PITCHB + kk * 2));
            #pragma unroll
            for (int nip = 0; nip < 2; nip++) {
                uint32_t b = bB + (uint32_t)(nip * 16 * PITCHB + kk * 2);
                uint32_t th[4];
                ldsm4(th, b);
                Bf[nip * 2][0] = th[0]; Bf[nip * 2][1] = th[1];
                Bf[nip * 2 + 1][0] = th[2]; Bf[nip * 2 + 1][1] = th[3];
            }
            #pragma unroll
            for (int mi = 0; mi < 4; mi++)
                #pragma unroll
                for (int ni = 0; ni < 4; ni++)
                    mma_f16(acc[mi][ni], Af[mi], Bf[ni]);
        }
        __syncthreads();
        if (t + STAGES < NT_K) load_tile(t % STAGES, t + STAGES);
        CP_COMMIT();
    }

    if (!fuse) {
        #pragma unroll
        for (int mi = 0; mi < 4; mi++) {
            #pragma unroll
            for (int half = 0; half < 2; half++) {
                size_t m = (size_t)(m0 + warpM * 64 + mi * 16 + gid + half * 8);
                #pragma unroll
                for (int ni = 0; ni < 4; ni++) {
                    int n = n0 + warpN * 32 + ni * 8 + 2 * tig;
                    float r0 = acc[mi][ni][half * 2 + 0] * WSCALE_INV;
                    float r1 = acc[mi][ni][half * 2 + 1] * WSCALE_INV;
                    float2 bs = *(const float2*)(bias + n);
                    float2 bb = *(const float2*)(base + m * DIM + n);
                    float2 o;
                    o.x = bb.x + sign * (r0 + bs.x);
                    o.y = bb.y + sign * (r1 + bs.y);
                    *(float2*)(outp + m * DIM + n) = o;
                    if (emit) {
                        float2 a2 = *(const float2*)(aN + n);
                        float2 c2 = *(const float2*)(cN + n);
                        __half2 h2 = __floats2half2_rn(a2.x * o.x + c2.x, a2.y * o.y + c2.y);
                        *(__half2*)(eHi + m * DIM + n) = h2;
                    }
                }
            }
        }
    } else {
        // ---- fused-mix epilogue (R12-proven) ----
        float* su1 = (float*)smem;                 // [128][MIXP]
        float* su2 = su1 + 128 * MIXP;             // [32][MIXP]
        #pragma unroll
        for (int mi = 0; mi < 4; mi++) {
            #pragma unroll
            for (int half = 0; half < 2; half++) {
                int ml = warpM * 64 + mi * 16 + gid + half * 8;
                size_t m = (size_t)(m0 + ml);
                #pragma unroll
                for (int ni = 0; ni < 4; ni++) {
                    int nl = warpN * 32 + ni * 8 + 2 * tig;
                    int n = n0 + nl;
                    float r0 = acc[mi][ni][half * 2 + 0] * WSCALE_INV;
                    float r1 = acc[mi][ni][half * 2 + 1] * WSCALE_INV;
                    float2 bs = *(const float2*)(bias + n);
                    float2 bb = *(const float2*)(base + m * DIM + n);
                    float2 o;
                    o.x = bb.x + sign * (r0 + bs.x);
                    o.y = bb.y + sign * (r1 + bs.y);
                    *(float2*)(su1 + ml * MIXP + nl) = o;
                }
            }
        }
        __syncthreads();

        const int i0 = n0 >> 5;
        #pragma unroll 1
        for (int chunk = 0; chunk < 4; chunk++) {
            #pragma unroll
            for (int l = tid; l < 1024; l += 256) {
                int mm = l >> 5;
                int f4 = l & 31;
                float4 v = *(const float4*)(u2mix +
                    (size_t)(m0 + chunk * 32 + mm) * DIM + n0 + f4 * 4);
                *(float4*)(su2 + mm * MIXP + f4 * 4) = v;
            }
            __syncthreads();
            #pragma unroll
            for (int pp = 0; pp < 8; pp++) {
                int mm = pp * 4 + (tid >> 6);
                int qq = tid & 63;
                int il = qq >> 4;
                int c0 = (qq & 15) * 4;
                int ig = i0 + il;
                const float* r1 = su1 + (chunk * 32 + mm) * MIXP + il * 32;
                const float* r2 = su2 + mm * MIXP + il * 32;
                int h = c0 >> 1;
                float4 o;
                if ((ig & 1) == 0) {
                    o.x = r1[h];     o.y = r2[h];
                    o.z = r1[h + 1]; o.w = r2[h + 1];
                } else {
                    o.x = r2[(h + 31) & 31];
                    o.y = r1[(h + 1) & 31];
                    o.z = r2[h];
                    o.w = r1[(h + 2) & 31];
                }
                *(float4*)(ymix + (size_t)(m0 + chunk * 32 + mm) * IMGE + ig * 64 + c0) = o;
            }
            __syncthreads();
        }
    }
}

// ---------------------------------------------------------------------------
extern "C" void kernel_launch(void* const* d_in, const int* in_sizes, int n_in,
                              void* d_out, int out_size)
{
    const float* x   = (const float*)d_in[0];
    const float* W1  = (const float*)d_in[2];
    const float* b1  = (const float*)d_in[3];
    const float* g1  = (const float*)d_in[4];
    const float* be1 = (const float*)d_in[5];
    const float* m1  = (const float*)d_in[6];
    const float* v1  = (const float*)d_in[7];
    const float* W3  = (const float*)d_in[8];
    const float* b3  = (const float*)d_in[9];
    const float* g3  = (const float*)d_in[10];
    const float* be3 = (const float*)d_in[11];
    const float* m3  = (const float*)d_in[12];
    const float* v3  = (const float*)d_in[13];
    const float* kop = (const float*)d_in[14];
    float* out = (float*)d_out;

    float *A, *B, *C, *D, *aF, *cF, *aG, *cG;
    __half *H0, *H1, *W1T, *W3T;
    cudaGetSymbolAddress((void**)&A,  g_A);
    cudaGetSymbolAddress((void**)&B,  g_B);
    cudaGetSymbolAddress((void**)&C,  g_C);
    cudaGetSymbolAddress((void**)&D,  g_D);
    cudaGetSymbolAddress((void**)&H0, g_H0);
    cudaGetSymbolAddress((void**)&H1, g_H1);
    cudaGetSymbolAddress((void**)&W1T, g_W1T);
    cudaGetSymbolAddress((void**)&W3T, g_W3T);
    cudaGetSymbolAddress((void**)&aF, g_aF);
    cudaGetSymbolAddress((void**)&cF, g_cF);
    cudaGetSymbolAddress((void**)&aG, g_aG);
    cudaGetSymbolAddress((void**)&cG, g_cG);

    static int smem_set = 0;
    if (!smem_set) {
        cudaFuncSetAttribute(gemm_tc_kernel, cudaFuncAttributeMaxDynamicSharedMemorySize,
                             SM_TOTAL);
        smem_set = 1;
    }

    dim3 ggrid(DIM / GN, NIMG / GM);           // (16, 24)
    const int UQ_BLKS = (int)(((size_t)NIMG * DIM / 4 + 255) / 256);
    dim3 wgrid(DIM / 32, DIM / 32), wblk(32, 8);

    bncoef_kernel<<<8, 256>>>(g1, be1, m1, v1, g3, be3, m3, v3);
    wprep_kernel<<<wgrid, wblk>>>(W1, W1T);
    wprep_kernel<<<wgrid, wblk>>>(W3, W3T);

    // ---- x prep: S0, S5, u1(A), u2(B), fp16 BN_F(u2) plane ----
    xprep_kernel<<<UQ_BLKS, 256>>>(x, out + S0, out + S5, A, B, aF, cF, H0);

    // ---- Encoder ----
    gemm_tc_kernel<<<ggrid, 256, SM_TOTAL>>>(H0, W1T, b1, A, A, +1.0f,
                                             aG, cG, H1, 1, nullptr, nullptr, 0);  // A = v1
    gemm_tc_kernel<<<ggrid, 256, SM_TOTAL>>>(H1, W3T, b3, B, B, +1.0f,
                                             aF, cF, H0, 0, nullptr, nullptr, 0);  // B = w2
    // phiX + slice + decoder split (C=w1, D=w2) + fp16 BN_G(w1) plane
    mixsplit_kernel<<<UQ_BLKS, 256>>>(A, B, out + S1, out + S6, C, D, aG, cG, H0);

    // ---- Decoder(phiX) ----
    gemm_tc_kernel<<<ggrid, 256, SM_TOTAL>>>(H0, W3T, b3, D, D, -1.0f,
                                             aF, cF, H1, 1, nullptr, nullptr, 0);  // D = v2
    gemm_tc_kernel<<<ggrid, 256, SM_TOTAL>>>(H1, W1T, b1, C, nullptr, -1.0f,
                                             nullptr, nullptr, nullptr, 0,
                                             D, out + S2, 1);                      // S2

    // ---- Koopman (+ fused split of kPhix: A=w1', B=w2', fp16 BN_G(w1')) ----
    koop_kernel<<<NIMG, 256>>>(out + S1, kop, out + S3, A, B, aG, cG, H0);

    // ---- Decoder(kPhix) ----
    gemm_tc_kernel<<<ggrid, 256, SM_TOTAL>>>(H0, W3T, b3, B, B, -1.0f,
                                             aF, cF, H1, 1, nullptr, nullptr, 0);  // B = v2'
    gemm_tc_kernel<<<ggrid, 256, SM_TOTAL>>>(H1, W1T, b1, A, nullptr, -1.0f,
                                             nullptr, nullptr, nullptr, 0,
                                             B, out + S4, 1);                      // S4
}